// round 11
// baseline (speedup 1.0000x reference)
#include <cuda_runtime.h>
#include <cuda_bf16.h>
#include <cstdint>

typedef unsigned long long ull;

#define E_DIM 128
#define NPG   32
#define TPB   256
#define PAD   132           // fp32 row stride for V_s (floats)
#define XSB   272           // bf16 tile row stride (bytes)
#define XH64  17408         // bytes per 64-row bf16 tile (64*272)
#define WHALF 34816         // bytes per 128-row bf16 tile (128*272)
#define WB    69632         // bytes per weight (hi+lo)

// smem byte offsets (104.5 KB total -> 2 CTAs/SM)
#define OFF_W    0          // 69632: weight hi/lo; V_s fp32 (33792) during attention
#define OFF_X    69632      // 34816: X hi/lo tiles; K_s fp32 staged; attn-out tiles
#define OFF_BIAS 104448     // 512 floats
#define SMEM_TOTAL 106496

__device__ __align__(1024) unsigned char g_wconv[4 * WB];
__device__ __align__(16) float g_qs[4194304];   // Q_s scratch (32768 x 128)
__device__ __align__(16) float g_ks[4194304];   // K_s scratch

// ---------- helpers ----------
__device__ __forceinline__ uint32_t s2u(const void* p) {
    uint32_t a;
    asm("{ .reg .u64 t; cvta.to.shared.u64 t, %1; cvt.u32.u64 %0, t; }" : "=r"(a) : "l"(p));
    return a;
}
__device__ __forceinline__ ull pack2(float lo, float hi) {
    ull r; asm("mov.b64 %0, {%1, %2};" : "=l"(r) : "f"(lo), "f"(hi)); return r;
}
__device__ __forceinline__ void unpack2(ull p, float& lo, float& hi) {
    asm("mov.b64 {%0, %1}, %2;" : "=f"(lo), "=f"(hi) : "l"(p));
}
__device__ __forceinline__ void ffma2(ull& d, ull a, ull b) {
    asm("fma.rn.f32x2 %0, %1, %2, %0;" : "+l"(d) : "l"(a), "l"(b));
}
__device__ __forceinline__ ull pack4bf(__nv_bfloat16 a, __nv_bfloat16 b,
                                       __nv_bfloat16 c, __nv_bfloat16 d) {
    uint32_t lo = ((uint32_t)__bfloat16_as_ushort(b) << 16) | __bfloat16_as_ushort(a);
    uint32_t hi = ((uint32_t)__bfloat16_as_ushort(d) << 16) | __bfloat16_as_ushort(c);
    return ((ull)hi << 32) | lo;
}
__device__ __forceinline__ void split4(float4 x, ull& hiw, ull& low) {
    __nv_bfloat16 h0 = __float2bfloat16(x.x), h1 = __float2bfloat16(x.y),
                  h2 = __float2bfloat16(x.z), h3 = __float2bfloat16(x.w);
    __nv_bfloat16 l0 = __float2bfloat16(x.x - __bfloat162float(h0));
    __nv_bfloat16 l1 = __float2bfloat16(x.y - __bfloat162float(h1));
    __nv_bfloat16 l2 = __float2bfloat16(x.z - __bfloat162float(h2));
    __nv_bfloat16 l3 = __float2bfloat16(x.w - __bfloat162float(h3));
    hiw = pack4bf(h0, h1, h2, h3);
    low = pack4bf(l0, l1, l2, l3);
}
__device__ __forceinline__ void ldsm4(uint32_t& r0, uint32_t& r1, uint32_t& r2,
                                      uint32_t& r3, uint32_t a) {
    asm volatile("ldmatrix.sync.aligned.m8n8.x4.shared.b16 {%0,%1,%2,%3}, [%4];"
                 : "=r"(r0), "=r"(r1), "=r"(r2), "=r"(r3) : "r"(a));
}
__device__ __forceinline__ void mma_bf16(float* c, const uint32_t* a,
                                         uint32_t b0, uint32_t b1) {
    asm volatile(
        "mma.sync.aligned.m16n8k16.row.col.f32.bf16.bf16.f32 "
        "{%0,%1,%2,%3}, {%4,%5,%6,%7}, {%8,%9}, {%0,%1,%2,%3};"
        : "+f"(c[0]), "+f"(c[1]), "+f"(c[2]), "+f"(c[3])
        : "r"(a[0]), "r"(a[1]), "r"(a[2]), "r"(a[3]), "r"(b0), "r"(b1));
}
__device__ __forceinline__ void cp16(uint32_t smem, const void* g) {
    asm volatile("cp.async.ca.shared.global [%0], [%1], 16;" :: "r"(smem), "l"(g) : "memory");
}
#define CP_COMMIT() asm volatile("cp.async.commit_group;" ::: "memory")
#define CP_WAIT0()  asm volatile("cp.async.wait_group 0;" ::: "memory")

// ---------- building blocks ----------
// X (64x128 f32, gmem) -> hi/lo bf16 tiles at OFF_X (256 threads)
__device__ __forceinline__ void convert_X(const float* __restrict__ gx, char* raw, int tid) {
    const int row  = tid >> 2;           // 0..63
    const int colb = (tid & 3) * 32;
#pragma unroll
    for (int i = 0; i < 8; i++) {
        const int col = colb + i * 4;
        float4 x = *reinterpret_cast<const float4*>(gx + row * E_DIM + col);
        ull hw, lw; split4(x, hw, lw);
        *(ull*)(raw + OFF_X + row * XSB + col * 2)        = hw;
        *(ull*)(raw + OFF_X + XH64 + row * XSB + col * 2) = lw;
    }
}
// async full weight copy: 4352 x 16B (256 threads x 17)
__device__ __forceinline__ void copy_W_async(int wsel, uint32_t sb, int tid) {
    const char* s = reinterpret_cast<const char*>(g_wconv) + wsel * WB;
    const uint32_t d = sb + OFF_W;
#pragma unroll
    for (int i = 0; i < 17; i++)
        cp16(d + (i * TPB + tid) * 16, s + (size_t)(i * TPB + tid) * 16);
    CP_COMMIT();
}

// 64x128 output, K=128, 3-split bf16 MMA, 16x64 warp tile (8 warps: 4x2 grid).
// Per k8 step: 10 ldsm4 -> 24 MMAs.
__device__ __forceinline__ void gemm8(char* raw, float acc[8][4], int w, int l) {
    const int wm = w >> 1, wn = w & 1;   // wm 0..3 (16 rows), wn 0..1 (64 cols)
    const uint32_t sb = s2u(raw);
#pragma unroll
    for (int s = 0; s < 8; s++)
#pragma unroll
        for (int i = 0; i < 4; i++) acc[s][i] = 0.f;
    const uint32_t aBase = sb + OFF_X + (wm * 16 + (l & 15)) * XSB + (l >> 4) * 16;
    const uint32_t bBase = sb + OFF_W +
        (wn * 64 + (l & 7) + ((l >> 4) & 1) * 8) * XSB + ((l >> 3) & 1) * 16;
#pragma unroll
    for (int k8 = 0; k8 < 8; k8++) {
        uint32_t ah[4], al[4];
        ldsm4(ah[0], ah[1], ah[2], ah[3], aBase + k8 * 32);
        ldsm4(al[0], al[1], al[2], al[3], aBase + XH64 + k8 * 32);
        uint32_t bh[16], bl[16];
#pragma unroll
        for (int sp = 0; sp < 4; sp++) {
            ldsm4(bh[4 * sp], bh[4 * sp + 1], bh[4 * sp + 2], bh[4 * sp + 3],
                  bBase + sp * 16 * XSB + k8 * 32);
            ldsm4(bl[4 * sp], bl[4 * sp + 1], bl[4 * sp + 2], bl[4 * sp + 3],
                  bBase + WHALF + sp * 16 * XSB + k8 * 32);
        }
#pragma unroll
        for (int sub = 0; sub < 8; sub++)
            mma_bf16(acc[sub], ah, bh[2 * sub], bh[2 * sub + 1]);   // hi*hi
#pragma unroll
        for (int sub = 0; sub < 8; sub++)
            mma_bf16(acc[sub], ah, bl[2 * sub], bl[2 * sub + 1]);   // hi*lo
#pragma unroll
        for (int sub = 0; sub < 8; sub++)
            mma_bf16(acc[sub], al, bh[2 * sub], bh[2 * sub + 1]);   // lo*hi
    }
}
__device__ __forceinline__ void epilogue8(const float acc[8][4], const float* bias,
                                          float scale, float* dst, int dstride,
                                          int w, int l) {
    const int wm = w >> 1, wn = w & 1;
    const int r0 = wm * 16 + (l >> 2);
#pragma unroll
    for (int sub = 0; sub < 8; sub++) {
        const int cb = wn * 64 + sub * 8 + (l & 3) * 2;
        float2 v;
        v.x = (acc[sub][0] + bias[cb]) * scale;
        v.y = (acc[sub][1] + bias[cb + 1]) * scale;
        *reinterpret_cast<float2*>(dst + r0 * dstride + cb) = v;
        v.x = (acc[sub][2] + bias[cb]) * scale;
        v.y = (acc[sub][3] + bias[cb + 1]) * scale;
        *reinterpret_cast<float2*>(dst + (r0 + 8) * dstride + cb) = v;
    }
}

// ---------- pre-kernel: weights f32 -> bf16 hi/lo tiles in g_wconv ----------
extern "C" __global__ void wconv_kernel(const float* __restrict__ wq,
                                        const float* __restrict__ wk,
                                        const float* __restrict__ wv,
                                        const float* __restrict__ wo) {
    const int idx = (blockIdx.x * blockDim.x + threadIdx.x) * 4;
    const int wsel = idx >> 14;
    const float* W = (wsel == 0) ? wq : (wsel == 1) ? wk : (wsel == 2) ? wv : wo;
    const int rem = idx & 16383;
    const int c = rem >> 7, k = rem & 127;
    float4 x = *reinterpret_cast<const float4*>(W + c * 128 + k);
    ull hw, lw; split4(x, hw, lw);
    *(ull*)(g_wconv + wsel * WB + c * XSB + k * 2)         = hw;
    *(ull*)(g_wconv + wsel * WB + WHALF + c * XSB + k * 2) = lw;
}

// ---------- main fused kernel: 2 graphs/CTA, 256 threads, 2 CTAs/SM ----------
extern "C" __global__ void __launch_bounds__(TPB, 2)
iattn_mma7_kernel(const float* __restrict__ query, const float* __restrict__ key,
                  const float* __restrict__ value,
                  const float* __restrict__ bq, const float* __restrict__ bk,
                  const float* __restrict__ bv, const float* __restrict__ bo,
                  float* __restrict__ out)
{
    extern __shared__ char raw[];
    const int tid = threadIdx.x;
    const int w = tid >> 5, l = tid & 31;
    const size_t base = (size_t)blockIdx.x * 64 * E_DIM;   // also QS/KS element base
    const uint32_t sb = s2u(raw);
    float* bias_s = reinterpret_cast<float*>(raw + OFF_BIAS);

    copy_W_async(0, sb, tid);
    {
        const float* b0 = (tid < 128) ? bq : bk;
        bias_s[tid] = b0[tid & 127];
        const float* b1 = (tid < 128) ? bv : bo;
        bias_s[tid + 256] = b1[tid & 127];
    }
    convert_X(query + base, raw, tid);
    CP_WAIT0();
    __syncthreads();                     // X(query) + Wq + bias visible

    float acc[8][4];

    // ---- Q projection -> gmem scratch ----
    gemm8(raw, acc, w, l);
    __syncthreads();                     // X/W reads done
    epilogue8(acc, bias_s, 0.25f, g_qs + base, E_DIM, w, l);
    copy_W_async(1, sb, tid);
    convert_X(key + base, raw, tid);
    CP_WAIT0();
    __syncthreads();

    // ---- K projection -> gmem scratch ----
    gemm8(raw, acc, w, l);
    __syncthreads();
    epilogue8(acc, bias_s + 128, 1.0f, g_ks + base, E_DIM, w, l);
    copy_W_async(2, sb, tid);
    convert_X(value + base, raw, tid);
    CP_WAIT0();
    __syncthreads();

    // ---- V projection -> V_s in (dead) W region smem ----
    gemm8(raw, acc, w, l);
    __syncthreads();                     // Wv + X(value tiles) reads done
    epilogue8(acc, bias_s + 256, 1.0f,
              reinterpret_cast<float*>(raw + OFF_W), PAD, w, l);
    // stage K_s back into (dead) X region: contiguous 32KB
    {
        const char* src = reinterpret_cast<const char*>(g_ks) + base * sizeof(float);
#pragma unroll
        for (int i = 0; i < 8; i++)
            cp16(sb + OFF_X + (i * TPB + tid) * 16, src + (size_t)(i * TPB + tid) * 16);
        CP_COMMIT();
    }
    CP_WAIT0();
    __syncthreads();                     // V_s + staged K_s visible

    // ---- attention: warp = head w (0..7); loop graphs g=0,1 ----
    float oall[2][16];
    {
        const float* Ks = reinterpret_cast<const float*>(raw + OFF_X);   // stride 128
        const float* Vs = reinterpret_cast<const float*>(raw + OFF_W);   // stride PAD
        const int c0 = w * 16;
#pragma unroll
        for (int g = 0; g < 2; g++) {
            const float* qp = g_qs + base + (g * NPG + l) * E_DIM + c0;
            float4 q0 = *reinterpret_cast<const float4*>(qp);
            float4 q1 = *reinterpret_cast<const float4*>(qp + 4);
            float4 q2 = *reinterpret_cast<const float4*>(qp + 8);
            float4 q3 = *reinterpret_cast<const float4*>(qp + 12);
            ull qa0 = pack2(q0.x, q0.y), qa1 = pack2(q0.z, q0.w);
            ull qb0 = pack2(q1.x, q1.y), qb1 = pack2(q1.z, q1.w);
            ull qc0 = pack2(q2.x, q2.y), qc1 = pack2(q2.z, q2.w);
            ull qd0 = pack2(q3.x, q3.y), qd1 = pack2(q3.z, q3.w);

            float sc[NPG];
            float mx = -1e30f;
#pragma unroll
            for (int j = 0; j < NPG; j++) {
                const float* kr = Ks + (g * NPG + j) * E_DIM + c0;
                ulonglong2 ka = *reinterpret_cast<const ulonglong2*>(kr);
                ulonglong2 kb = *reinterpret_cast<const ulonglong2*>(kr + 4);
                ulonglong2 kc = *reinterpret_cast<const ulonglong2*>(kr + 8);
                ulonglong2 kd = *reinterpret_cast<const ulonglong2*>(kr + 12);
                ull t2 = 0ULL;
                ffma2(t2, qa0, ka.x); ffma2(t2, qa1, ka.y);
                ffma2(t2, qb0, kb.x); ffma2(t2, qb1, kb.y);
                ffma2(t2, qc0, kc.x); ffma2(t2, qc1, kc.y);
                ffma2(t2, qd0, kd.x); ffma2(t2, qd1, kd.y);
                float tl, th; unpack2(t2, tl, th);
                const float t = tl + th;
                sc[j] = t;
                mx = fmaxf(mx, t);
            }
            float sum = 0.f;
#pragma unroll
            for (int j = 0; j < NPG; j++) { sc[j] = __expf(sc[j] - mx); sum += sc[j]; }
            const float inv = 1.0f / sum;

            ull o2[8];
#pragma unroll
            for (int i = 0; i < 8; i++) o2[i] = 0ULL;
#pragma unroll
            for (int j = 0; j < NPG; j++) {
                const ull p2 = pack2(sc[j], sc[j]);
                const float* vr = Vs + (g * NPG + j) * PAD + c0;
                ulonglong2 va = *reinterpret_cast<const ulonglong2*>(vr);
                ulonglong2 vb = *reinterpret_cast<const ulonglong2*>(vr + 4);
                ulonglong2 vc = *reinterpret_cast<const ulonglong2*>(vr + 8);
                ulonglong2 vd = *reinterpret_cast<const ulonglong2*>(vr + 12);
                ffma2(o2[0], p2, va.x); ffma2(o2[1], p2, va.y);
                ffma2(o2[2], p2, vb.x); ffma2(o2[3], p2, vb.y);
                ffma2(o2[4], p2, vc.x); ffma2(o2[5], p2, vc.y);
                ffma2(o2[6], p2, vd.x); ffma2(o2[7], p2, vd.y);
            }
#pragma unroll
            for (int i = 0; i < 8; i++) {
                float lo, hi; unpack2(o2[i], lo, hi);
                oall[g][2 * i]     = lo * inv;
                oall[g][2 * i + 1] = hi * inv;
            }
        }
    }
    __syncthreads();                     // all K_s/V_s reads done

    copy_W_async(3, sb, tid);            // Wo into (dead) W region
    // attn-out bf16 hi/lo tiles into (dead) X region
    {
        const int c0 = w * 16;
#pragma unroll
        for (int g = 0; g < 2; g++) {
            const int row = g * NPG + l;
#pragma unroll
            for (int p = 0; p < 4; p++) {
                float4 x = make_float4(oall[g][4 * p], oall[g][4 * p + 1],
                                       oall[g][4 * p + 2], oall[g][4 * p + 3]);
                ull hw, lw; split4(x, hw, lw);
                const int col = c0 + 4 * p;
                *(ull*)(raw + OFF_X + row * XSB + col * 2)        = hw;
                *(ull*)(raw + OFF_X + XH64 + row * XSB + col * 2) = lw;
            }
        }
    }
    CP_WAIT0();
    __syncthreads();                     // tiles + Wo visible

    // ---- out projection -> gmem ----
    gemm8(raw, acc, w, l);
    epilogue8(acc, bias_s + 384, 1.0f, out + base, E_DIM, w, l);
}

extern "C" void kernel_launch(void* const* d_in, const int* in_sizes, int n_in,
                              void* d_out, int out_size)
{
    const float* query = (const float*)d_in[0];
    const float* key_  = (const float*)d_in[1];
    const float* value = (const float*)d_in[2];
    const float* wq    = (const float*)d_in[3];
    const float* wk    = (const float*)d_in[4];
    const float* wv    = (const float*)d_in[5];
    const float* bq    = (const float*)d_in[6];
    const float* bk    = (const float*)d_in[7];
    const float* bv    = (const float*)d_in[8];
    const float* wo    = (const float*)d_in[9];
    const float* bo    = (const float*)d_in[10];
    float* out = (float*)d_out;

    const int N = in_sizes[0] / E_DIM;   // total nodes
    const int grid = N / 64;             // 2 graphs per CTA

    wconv_kernel<<<64, 256>>>(wq, wk, wv, wo);

    cudaFuncSetAttribute(iattn_mma7_kernel,
                         cudaFuncAttributeMaxDynamicSharedMemorySize, SMEM_TOTAL);
    iattn_mma7_kernel<<<grid, TPB, SMEM_TOTAL>>>(
        query, key_, value, bq, bk, bv, bo, out);
}